// round 1
// baseline (speedup 1.0000x reference)
#include <cuda_runtime.h>
#include <math.h>

// Problem constants (fixed shapes)
#define CC      128          // channels
#define TN      64           // voxels per tile
#define NCOND   4
#define NHEADS  8
#define NVOX    32768        // 32*32*32
#define NTILES  512          // NVOX / TN
#define NB      2
#define NGROUPS 8
#define GSIZE   16           // channels per group

// shared memory layout (floats)
#define SW   (CC*CC)         // 16384 — one weight matrix
#define SY   (CC*TN)         // 8192  — activation tile
#define SSP  (16*TN)         // 1024  — partial scores (cy, n)
#define SHN  (NHEADS*TN)     // 512   — per-(head,voxel) softmax state

// scratch for deterministic GroupNorm reduction (no allocations allowed)
__device__ float  g_sum[NB*NGROUPS*NTILES];
__device__ float  g_sq [NB*NGROUPS*NTILES];
__device__ float2 g_stats[NB*NGROUPS];

// ---------------------------------------------------------------------------
// cooperative loaders
// ---------------------------------------------------------------------------
__device__ __forceinline__ void load_w_smem(float* dst, const float* __restrict__ src, int tid) {
    // 16384 floats = 4096 float4, 256 threads -> 16 each, fully coalesced
    const float4* s4 = (const float4*)src;
    float4* d4 = (float4*)dst;
#pragma unroll
    for (int r = 0; r < 16; r++) {
        int idx = r*256 + tid;
        d4[idx] = s4[idx];
    }
}

__device__ __forceinline__ void load_tile(float* dst, const float* __restrict__ src, int tid) {
    // 128 rows x 64 floats; src row stride = NVOX floats (channel-major), coalesced 256B/half-warp
#pragma unroll
    for (int r = 0; r < 8; r++) {
        int idx = r*256 + tid;          // 0..2047
        int row = idx >> 4;
        int c4  = idx & 15;
        float4 v = *(const float4*)(src + (size_t)row*NVOX + c4*4);
        *(float4*)(dst + row*TN + c4*4) = v;
    }
}

// ---------------------------------------------------------------------------
// register-blocked GEMM microkernel: acc[8][4] += W[co0..co0+8, :] @ Y[:, n0..n0+4]
// W row-major [128][128] in smem (warp-broadcast reads), Y [128][64] in smem.
// ---------------------------------------------------------------------------
__device__ __forceinline__ void gemm_acc(float acc[8][4], const float* __restrict__ wt,
                                         const float* __restrict__ ybuf, int co0, int n0) {
#pragma unroll 2
    for (int kc = 0; kc < 32; kc++) {
        float4 y0 = *(const float4*)(ybuf + (4*kc+0)*TN + n0);
        float4 y1 = *(const float4*)(ybuf + (4*kc+1)*TN + n0);
        float4 y2 = *(const float4*)(ybuf + (4*kc+2)*TN + n0);
        float4 y3 = *(const float4*)(ybuf + (4*kc+3)*TN + n0);
#pragma unroll
        for (int i = 0; i < 8; i++) {
            float4 w = *(const float4*)(wt + (co0+i)*CC + 4*kc);
            acc[i][0] = fmaf(w.x, y0.x, acc[i][0]);
            acc[i][1] = fmaf(w.x, y0.y, acc[i][1]);
            acc[i][2] = fmaf(w.x, y0.z, acc[i][2]);
            acc[i][3] = fmaf(w.x, y0.w, acc[i][3]);
            acc[i][0] = fmaf(w.y, y1.x, acc[i][0]);
            acc[i][1] = fmaf(w.y, y1.y, acc[i][1]);
            acc[i][2] = fmaf(w.y, y1.z, acc[i][2]);
            acc[i][3] = fmaf(w.y, y1.w, acc[i][3]);
            acc[i][0] = fmaf(w.z, y2.x, acc[i][0]);
            acc[i][1] = fmaf(w.z, y2.y, acc[i][1]);
            acc[i][2] = fmaf(w.z, y2.z, acc[i][2]);
            acc[i][3] = fmaf(w.z, y2.w, acc[i][3]);
            acc[i][0] = fmaf(w.w, y3.x, acc[i][0]);
            acc[i][1] = fmaf(w.w, y3.y, acc[i][1]);
            acc[i][2] = fmaf(w.w, y3.z, acc[i][2]);
            acc[i][3] = fmaf(w.w, y3.w, acc[i][3]);
        }
    }
}

// ---------------------------------------------------------------------------
// Kernel 1: fused QKV projections + online-softmax cross-attention + O-proj
//           + residual; emits pre-GN output and per-(batch,group) partial sums.
// Block: 256 threads, tile = all 128 channels x 64 voxels.
// Thread (cy = tid/16, nx = tid%16) owns channels [8cy,8cy+8) x voxels [4nx,4nx+4).
// All 8 channels of a thread are inside one head (h = cy/2); all 32 channels of a
// warp are inside one GroupNorm group (g = warp id).
// ---------------------------------------------------------------------------
extern "C" __global__ void __launch_bounds__(256, 1)
attn_fused(const float* __restrict__ skip, const float* __restrict__ dec,
           const float* __restrict__ wq, const float* __restrict__ wk,
           const float* __restrict__ wv,
           const float* __restrict__ bq, const float* __restrict__ bk,
           const float* __restrict__ bv,
           const float* __restrict__ wo, const float* __restrict__ bo,
           float* __restrict__ out)
{
    extern __shared__ float sm[];
    float* wtA  = sm;             // weight A: Wq -> Wk -> Wo
    float* wtB  = wtA + SW;       // weight B: Wv
    float* ybuf = wtB + SW;       // activation tile: X -> Y_c -> O_attn
    float* sp   = ybuf + SY;      // partial scores [16][64]
    float* ms   = sp + SSP;       // running max   [8][64]
    float* ls   = ms + SHN;       // running sumexp[8][64]
    float* cs   = ls + SHN;       // correction    [8][64]
    float* pp   = cs + SHN;       // p = exp(s-m)  [8][64]

    const int tid  = threadIdx.x;
    const int tile = blockIdx.x;
    const int b    = blockIdx.y;
    const int cy = tid >> 4, nx = tid & 15;
    const int co0 = cy*8, n0 = nx*4;
    const int h = cy >> 1;

    const size_t voxBase = (size_t)tile * TN;
    const float* decb = dec + (size_t)b*CC*NVOX + voxBase;
    const float* skipb = skip + (size_t)b*NCOND*CC*NVOX + voxBase;

    // Phase 0: X tile + Wq, init softmax state
    load_tile(ybuf, decb, tid);
    load_w_smem(wtA, wq, tid);
    ms[tid] = -INFINITY; ms[tid+256] = -INFINITY;
    ls[tid] = 0.0f;      ls[tid+256] = 0.0f;
    __syncthreads();

    // Q projection (kept in registers)
    float q[8][4];
#pragma unroll
    for (int i = 0; i < 8; i++) {
        float bias = __ldg(&bq[co0+i]);
#pragma unroll
        for (int j = 0; j < 4; j++) q[i][j] = bias;
    }
    gemm_acc(q, wtA, ybuf, co0, n0);

    float oacc[8][4];
#pragma unroll
    for (int i = 0; i < 8; i++)
#pragma unroll
        for (int j = 0; j < 4; j++) oacc[i][j] = 0.0f;

    __syncthreads();                       // done reading Wq (wtA) and X (ybuf)
    load_w_smem(wtA, wk, tid);
    load_w_smem(wtB, wv, tid);

    // cond loop with online softmax
    for (int c = 0; c < NCOND; c++) {
        __syncthreads();                   // ybuf free / weights staged
        load_tile(ybuf, skipb + (size_t)c*CC*NVOX, tid);
        __syncthreads();

        // K = Wk @ Y + bk, fused with partial score q.k
        float kv[8][4];
#pragma unroll
        for (int i = 0; i < 8; i++) {
            float bias = __ldg(&bk[co0+i]);
#pragma unroll
            for (int j = 0; j < 4; j++) kv[i][j] = bias;
        }
        gemm_acc(kv, wtA, ybuf, co0, n0);

        float ps[4] = {0.f, 0.f, 0.f, 0.f};
#pragma unroll
        for (int i = 0; i < 8; i++)
#pragma unroll
            for (int j = 0; j < 4; j++) ps[j] = fmaf(q[i][j], kv[i][j], ps[j]);
#pragma unroll
        for (int j = 0; j < 4; j++) sp[cy*TN + n0 + j] = ps[j];
        __syncthreads();

        // softmax state update: 512 (head,voxel) items over 256 threads
#pragma unroll
        for (int t = tid; t < 2*256; t += 256) {
            int hh = t >> 6, nn = t & 63;
            float s  = (sp[(2*hh)*TN + nn] + sp[(2*hh+1)*TN + nn]) * 0.25f;
            float mo = ms[t];
            float mn = fmaxf(mo, s);
            float corr = __expf(mo - mn);
            float pv   = __expf(s - mn);
            ls[t] = ls[t]*corr + pv;
            ms[t] = mn;
            cs[t] = corr;
            pp[t] = pv;
        }
        __syncthreads();

        // V = Wv @ Y + bv (reuse kv registers)
#pragma unroll
        for (int i = 0; i < 8; i++) {
            float bias = __ldg(&bv[co0+i]);
#pragma unroll
            for (int j = 0; j < 4; j++) kv[i][j] = bias;
        }
        gemm_acc(kv, wtB, ybuf, co0, n0);

        // oacc = oacc*corr + p*V
#pragma unroll
        for (int j = 0; j < 4; j++) {
            float corr = cs[h*TN + n0 + j];
            float pv   = pp[h*TN + n0 + j];
#pragma unroll
            for (int i = 0; i < 8; i++)
                oacc[i][j] = fmaf(oacc[i][j], corr, pv*kv[i][j]);
        }
    }

    // finalize attention output -> ybuf; stage Wo
    __syncthreads();                       // everyone done with ybuf (V gemm)
#pragma unroll
    for (int j = 0; j < 4; j++) {
        float inv = 1.0f / ls[h*TN + n0 + j];
#pragma unroll
        for (int i = 0; i < 8; i++)
            ybuf[(co0+i)*TN + n0 + j] = oacc[i][j] * inv;
    }
    load_w_smem(wtA, wo, tid);             // wtA (Wk) no longer needed
    __syncthreads();

    // O projection + bias + residual
    float ov[8][4];
#pragma unroll
    for (int i = 0; i < 8; i++) {
        float bias = __ldg(&bo[co0+i]);
#pragma unroll
        for (int j = 0; j < 4; j++) ov[i][j] = bias;
    }
    gemm_acc(ov, wtA, ybuf, co0, n0);

    float* outb = out + (size_t)b*CC*NVOX + voxBase;
    float s1 = 0.0f, s2 = 0.0f;
#pragma unroll
    for (int i = 0; i < 8; i++) {
        float4 r = *(const float4*)(decb + (size_t)(co0+i)*NVOX + n0);
        float v0 = ov[i][0] + r.x;
        float v1 = ov[i][1] + r.y;
        float v2 = ov[i][2] + r.z;
        float v3 = ov[i][3] + r.w;
        float4 wv4 = make_float4(v0, v1, v2, v3);
        *(float4*)(outb + (size_t)(co0+i)*NVOX + n0) = wv4;
        s1 += (v0 + v1) + (v2 + v3);
        s2 += fmaf(v0, v0, v1*v1) + fmaf(v2, v2, v3*v3);
    }

    // deterministic GroupNorm partials: whole warp belongs to group g = warp id
#pragma unroll
    for (int off = 16; off; off >>= 1) {
        s1 += __shfl_xor_sync(0xffffffffu, s1, off);
        s2 += __shfl_xor_sync(0xffffffffu, s2, off);
    }
    int warp = tid >> 5;
    if ((tid & 31) == 0) {
        int slot = (b*NGROUPS + warp)*NTILES + tile;
        g_sum[slot] = s1;
        g_sq[slot]  = s2;
    }
}

// ---------------------------------------------------------------------------
// Kernel 2: reduce per-tile partials into per-(batch,group) mean / rstd
// ---------------------------------------------------------------------------
extern "C" __global__ void gn_stats() {
    __shared__ float sh1[256], sh2[256];
    const int bg = blockIdx.x;        // 0..15
    const int tid = threadIdx.x;
    const float* ps = g_sum + bg*NTILES;
    const float* pq = g_sq  + bg*NTILES;
    float s1 = ps[tid] + ps[tid+256];
    float s2 = pq[tid] + pq[tid+256];
    sh1[tid] = s1; sh2[tid] = s2;
    __syncthreads();
    for (int off = 128; off; off >>= 1) {
        if (tid < off) { sh1[tid] += sh1[tid+off]; sh2[tid] += sh2[tid+off]; }
        __syncthreads();
    }
    if (tid == 0) {
        const float cnt = (float)(GSIZE*NVOX);     // 524288
        float mean = sh1[0] / cnt;
        float var  = sh2[0] / cnt - mean*mean;
        g_stats[bg] = make_float2(mean, rsqrtf(var + 1e-5f));
    }
}

// ---------------------------------------------------------------------------
// Kernel 3: apply GroupNorm affine in place
// ---------------------------------------------------------------------------
extern "C" __global__ void gn_apply(float* __restrict__ out,
                                    const float* __restrict__ gamma,
                                    const float* __restrict__ beta) {
    size_t idx4 = (size_t)blockIdx.x * blockDim.x + threadIdx.x;   // float4 index
    size_t elem = idx4 * 4;
    int b = (int)(elem >> 22);                 // CC*NVOX = 2^22
    int c = (int)((elem >> 15) & 127);         // NVOX = 2^15
    float2 st = g_stats[b*NGROUPS + (c >> 4)];
    float ga = __ldg(&gamma[c]);
    float be = __ldg(&beta[c]);
    float4 v = *(float4*)(out + elem);
    float sc = st.y * ga;
    v.x = (v.x - st.x)*sc + be;
    v.y = (v.y - st.x)*sc + be;
    v.z = (v.z - st.x)*sc + be;
    v.w = (v.w - st.x)*sc + be;
    *(float4*)(out + elem) = v;
}

// ---------------------------------------------------------------------------
extern "C" void kernel_launch(void* const* d_in, const int* in_sizes, int n_in,
                              void* d_out, int out_size) {
    const float* skip  = (const float*)d_in[0];
    const float* dec   = (const float*)d_in[1];
    const float* wq    = (const float*)d_in[2];
    const float* wk    = (const float*)d_in[3];
    const float* wv    = (const float*)d_in[4];
    const float* bq    = (const float*)d_in[5];
    const float* bk    = (const float*)d_in[6];
    const float* bv    = (const float*)d_in[7];
    const float* wo    = (const float*)d_in[8];
    const float* bo    = (const float*)d_in[9];
    const float* gamma = (const float*)d_in[10];
    const float* beta  = (const float*)d_in[11];
    float* out = (float*)d_out;

    const size_t smem = (size_t)(2*SW + SY + SSP + 4*SHN) * sizeof(float); // 176128 B
    cudaFuncSetAttribute(attn_fused, cudaFuncAttributeMaxDynamicSharedMemorySize, (int)smem);

    dim3 grid(NTILES, NB);
    attn_fused<<<grid, 256, smem>>>(skip, dec, wq, wk, wv, bq, bk, bv, wo, bo, out);
    gn_stats<<<NB*NGROUPS, 256>>>();
    gn_apply<<<(NB*CC*NVOX/4)/256, 256>>>(out, gamma, beta);
}

// round 2
// speedup vs baseline: 1.0760x; 1.0760x over previous
#include <cuda_runtime.h>
#include <math.h>

// Problem constants (fixed shapes)
#define CC      128          // channels
#define TN      64           // voxels per tile
#define NCOND   4
#define NHEADS  8
#define NVOX    32768        // 32*32*32
#define NTILES  512          // NVOX / TN
#define NB      2
#define NGROUPS 8
#define GSIZE   16           // channels per group

// shared memory layout (floats)
#define SW   (CC*CC)         // 16384 — one weight matrix (transposed: [k][co])
#define SY   (CC*TN)         // 8192  — activation tile
#define SSP  (16*TN)         // 1024  — partial scores (cy, n)
#define SHN  (NHEADS*TN)     // 512   — per-(head,voxel) softmax state

typedef unsigned long long ull;

// scratch (no allocations allowed)
__device__ float  g_wT[4][CC*CC];          // transposed weights: Wq,Wk,Wv,Wo as [k][co]
__device__ float  g_sum[NB*NGROUPS*NTILES];
__device__ float  g_sq [NB*NGROUPS*NTILES];
__device__ float2 g_stats[NB*NGROUPS];

// ---------------------------------------------------------------------------
// packed f32x2 helpers (Blackwell FFMA2 path)
// ---------------------------------------------------------------------------
__device__ __forceinline__ ull dup2(float a) {
    ull r; asm("mov.b64 %0, {%1, %1};" : "=l"(r) : "f"(a)); return r;
}
__device__ __forceinline__ ull pack2(float a, float b) {
    ull r; asm("mov.b64 %0, {%1, %2};" : "=l"(r) : "f"(a), "f"(b)); return r;
}
__device__ __forceinline__ float2 unpack2(ull v) {
    float2 r; asm("mov.b64 {%0, %1}, %2;" : "=f"(r.x), "=f"(r.y) : "l"(v)); return r;
}
__device__ __forceinline__ void ffma2(ull& d, ull a, ull b) {
    asm("fma.rn.f32x2 %0, %1, %2, %0;" : "+l"(d) : "l"(a), "l"(b));
}
__device__ __forceinline__ ull ffma2_3(ull a, ull b, ull c) {
    ull d; asm("fma.rn.f32x2 %0, %1, %2, %3;" : "=l"(d) : "l"(a), "l"(b), "l"(c)); return d;
}
__device__ __forceinline__ ull fmul2(ull a, ull b) {
    ull d; asm("mul.rn.f32x2 %0, %1, %2;" : "=l"(d) : "l"(a), "l"(b)); return d;
}

// ---------------------------------------------------------------------------
// Kernel 0: transpose the 4 weight matrices into [k][co] layout (runs once per
// launch; ~3us). Makes channel pairs (co, co+1) contiguous for b64 loads.
// ---------------------------------------------------------------------------
extern "C" __global__ void transpose_w(const float* __restrict__ wq,
                                       const float* __restrict__ wk,
                                       const float* __restrict__ wv,
                                       const float* __restrict__ wo) {
    int idx = blockIdx.x * 256 + threadIdx.x;   // 0..65535
    int m = idx >> 14;
    int e = idx & 16383;
    int r = e >> 7, c = e & 127;                // src row r, col c
    const float* src = (m == 0) ? wq : (m == 1) ? wk : (m == 2) ? wv : wo;
    g_wT[m][c*CC + r] = src[r*CC + c];
}

// ---------------------------------------------------------------------------
// cooperative loaders
// ---------------------------------------------------------------------------
__device__ __forceinline__ void load_w_smem(float* dst, const float* __restrict__ src, int tid) {
    const float4* s4 = (const float4*)src;
    float4* d4 = (float4*)dst;
#pragma unroll
    for (int r = 0; r < 16; r++) {
        int idx = r*256 + tid;
        d4[idx] = s4[idx];
    }
}

__device__ __forceinline__ void load_tile(float* dst, const float* __restrict__ src, int tid) {
#pragma unroll
    for (int r = 0; r < 8; r++) {
        int idx = r*256 + tid;          // 0..2047
        int row = idx >> 4;
        int c4  = idx & 15;
        float4 v = *(const float4*)(src + (size_t)row*NVOX + c4*4);
        *(float4*)(dst + row*TN + c4*4) = v;
    }
}

// ---------------------------------------------------------------------------
// packed register-blocked GEMM: acc2[p][j] (+)= W[co0+2p..2p+1, :] @ Y[:, n0+j]
// wt: transposed weights [k][co] in smem (reads broadcast),
// Y [128][64] in smem. acc2 lanes = channel pair (co0+2p, co0+2p+1).
// 16 FFMA2 + 3 LDS.128 + 4 dup per k-step.
// ---------------------------------------------------------------------------
__device__ __forceinline__ void gemm_acc2(ull acc[4][4], const float* __restrict__ wt,
                                          const float* __restrict__ yb, int co0, int n0) {
    const float* wp = wt + co0;
    const float* yp = yb + n0;
#pragma unroll 4
    for (int k = 0; k < CC; k++) {
        float4 y = *(const float4*)(yp + k*TN);
        ulonglong2 wA = *(const ulonglong2*)(wp + k*CC);       // (co0,co0+1),(co0+2,co0+3)
        ulonglong2 wB = *(const ulonglong2*)(wp + k*CC + 4);   // (co0+4,co0+5),(co0+6,co0+7)
        ull y0 = dup2(y.x), y1 = dup2(y.y), y2 = dup2(y.z), y3 = dup2(y.w);
        ffma2(acc[0][0], wA.x, y0); ffma2(acc[0][1], wA.x, y1);
        ffma2(acc[0][2], wA.x, y2); ffma2(acc[0][3], wA.x, y3);
        ffma2(acc[1][0], wA.y, y0); ffma2(acc[1][1], wA.y, y1);
        ffma2(acc[1][2], wA.y, y2); ffma2(acc[1][3], wA.y, y3);
        ffma2(acc[2][0], wB.x, y0); ffma2(acc[2][1], wB.x, y1);
        ffma2(acc[2][2], wB.x, y2); ffma2(acc[2][3], wB.x, y3);
        ffma2(acc[3][0], wB.y, y0); ffma2(acc[3][1], wB.y, y1);
        ffma2(acc[3][2], wB.y, y2); ffma2(acc[3][3], wB.y, y3);
    }
}

__device__ __forceinline__ void init_bias2(ull acc[4][4], const float* __restrict__ bias, int co0) {
#pragma unroll
    for (int p = 0; p < 4; p++) {
        ull bv = pack2(__ldg(&bias[co0+2*p]), __ldg(&bias[co0+2*p+1]));
#pragma unroll
        for (int j = 0; j < 4; j++) acc[p][j] = bv;
    }
}

// ---------------------------------------------------------------------------
// Kernel 1: fused QKV projections + online-softmax cross-attention + O-proj
//           + residual; emits pre-GN output and per-(batch,group) partials.
// Block 256 thr; thread (cy=tid/16, nx=tid%16) owns channels [8cy,8cy+8) x
// voxels [4nx,4nx+4). Thread's channels sit in one head (h=cy/2); a warp's 32
// channels sit in one GN group (g = warp id).
// ---------------------------------------------------------------------------
extern "C" __global__ void __launch_bounds__(256, 1)
attn_fused(const float* __restrict__ skip, const float* __restrict__ dec,
           const float* __restrict__ bq, const float* __restrict__ bk,
           const float* __restrict__ bv,
           const float* __restrict__ bo,
           float* __restrict__ out)
{
    extern __shared__ float sm[];
    float* wtA  = sm;             // weight A: WqT -> WkT -> WoT
    float* wtB  = wtA + SW;       // weight B: WvT
    float* ybuf = wtB + SW;       // activation tile: X -> Y_c -> O_attn
    float* sp   = ybuf + SY;      // partial scores [16][64]
    float* ms   = sp + SSP;       // running max   [8][64]
    float* ls   = ms + SHN;       // running sumexp[8][64]
    float* cs   = ls + SHN;       // correction    [8][64]
    float* pp   = cs + SHN;       // p = exp(s-m)  [8][64]

    const int tid  = threadIdx.x;
    const int tile = blockIdx.x;
    const int b    = blockIdx.y;
    const int cy = tid >> 4, nx = tid & 15;
    const int co0 = cy*8, n0 = nx*4;
    const int h = cy >> 1;

    const size_t voxBase = (size_t)tile * TN;
    const float* decb  = dec  + (size_t)b*CC*NVOX + voxBase;
    const float* skipb = skip + (size_t)b*NCOND*CC*NVOX + voxBase;

    // Phase 0: X tile + WqT, init softmax state
    load_tile(ybuf, decb, tid);
    load_w_smem(wtA, g_wT[0], tid);
    ms[tid] = -INFINITY; ms[tid+256] = -INFINITY;
    ls[tid] = 0.0f;      ls[tid+256] = 0.0f;
    __syncthreads();

    // Q projection (kept packed in registers)
    ull q2[4][4];
    init_bias2(q2, bq, co0);
    gemm_acc2(q2, wtA, ybuf, co0, n0);

    ull oacc2[4][4];
#pragma unroll
    for (int p = 0; p < 4; p++)
#pragma unroll
        for (int j = 0; j < 4; j++) oacc2[p][j] = 0ull;

    __syncthreads();                       // done reading WqT (wtA) and X (ybuf)
    load_w_smem(wtA, g_wT[1], tid);        // WkT
    load_w_smem(wtB, g_wT[2], tid);        // WvT

    // cond loop with online softmax
    for (int c = 0; c < NCOND; c++) {
        __syncthreads();                   // ybuf free / weights staged
        load_tile(ybuf, skipb + (size_t)c*CC*NVOX, tid);
        __syncthreads();

        // K = Wk @ Y + bk, fused with partial score q.k
        ull kv2[4][4];
        init_bias2(kv2, bk, co0);
        gemm_acc2(kv2, wtA, ybuf, co0, n0);

        ull ps2[4] = {0ull, 0ull, 0ull, 0ull};
#pragma unroll
        for (int p = 0; p < 4; p++)
#pragma unroll
            for (int j = 0; j < 4; j++) ffma2(ps2[j], q2[p][j], kv2[p][j]);
#pragma unroll
        for (int j = 0; j < 4; j++) {
            float2 v = unpack2(ps2[j]);
            sp[cy*TN + n0 + j] = v.x + v.y;
        }
        __syncthreads();

        // softmax state update: 512 (head,voxel) items over 256 threads
#pragma unroll
        for (int t = tid; t < 2*256; t += 256) {
            int hh = t >> 6, nn = t & 63;
            float s  = (sp[(2*hh)*TN + nn] + sp[(2*hh+1)*TN + nn]) * 0.25f;
            float mo = ms[t];
            float mn = fmaxf(mo, s);
            float corr = __expf(mo - mn);
            float pv   = __expf(s - mn);
            ls[t] = ls[t]*corr + pv;
            ms[t] = mn;
            cs[t] = corr;
            pp[t] = pv;
        }
        __syncthreads();

        // V = Wv @ Y + bv (reuse kv2 registers)
        init_bias2(kv2, bv, co0);
        gemm_acc2(kv2, wtB, ybuf, co0, n0);

        // oacc = oacc*corr + p*V  (packed)
#pragma unroll
        for (int j = 0; j < 4; j++) {
            ull corr2 = dup2(cs[h*TN + n0 + j]);
            ull pv2   = dup2(pp[h*TN + n0 + j]);
#pragma unroll
            for (int p = 0; p < 4; p++)
                oacc2[p][j] = ffma2_3(oacc2[p][j], corr2, fmul2(pv2, kv2[p][j]));
        }
    }

    // finalize attention output -> ybuf; stage WoT
    __syncthreads();                       // everyone done with ybuf (V gemm)
#pragma unroll
    for (int j = 0; j < 4; j++) {
        float inv = 1.0f / ls[h*TN + n0 + j];
#pragma unroll
        for (int p = 0; p < 4; p++) {
            float2 o = unpack2(oacc2[p][j]);
            ybuf[(co0+2*p  )*TN + n0 + j] = o.x * inv;
            ybuf[(co0+2*p+1)*TN + n0 + j] = o.y * inv;
        }
    }
    load_w_smem(wtA, g_wT[3], tid);        // WoT (wtA free)
    __syncthreads();

    // O projection + bias + residual
    ull ov2[4][4];
    init_bias2(ov2, bo, co0);
    gemm_acc2(ov2, wtA, ybuf, co0, n0);

    float* outb = out + (size_t)b*CC*NVOX + voxBase;
    float s1 = 0.0f, s2 = 0.0f;
#pragma unroll
    for (int p = 0; p < 4; p++) {
        float4 r0 = *(const float4*)(decb + (size_t)(co0+2*p  )*NVOX + n0);
        float4 r1 = *(const float4*)(decb + (size_t)(co0+2*p+1)*NVOX + n0);
        float2 a0 = unpack2(ov2[p][0]);
        float2 a1 = unpack2(ov2[p][1]);
        float2 a2 = unpack2(ov2[p][2]);
        float2 a3 = unpack2(ov2[p][3]);
        float u0 = a0.x + r0.x, u1 = a1.x + r0.y, u2 = a2.x + r0.z, u3 = a3.x + r0.w;
        float w0 = a0.y + r1.x, w1 = a1.y + r1.y, w2 = a2.y + r1.z, w3 = a3.y + r1.w;
        *(float4*)(outb + (size_t)(co0+2*p  )*NVOX + n0) = make_float4(u0, u1, u2, u3);
        *(float4*)(outb + (size_t)(co0+2*p+1)*NVOX + n0) = make_float4(w0, w1, w2, w3);
        s1 += (u0 + u1) + (u2 + u3) + (w0 + w1) + (w2 + w3);
        s2 += fmaf(u0, u0, u1*u1) + fmaf(u2, u2, u3*u3)
            + fmaf(w0, w0, w1*w1) + fmaf(w2, w2, w3*w3);
    }

    // deterministic GroupNorm partials: whole warp belongs to group g = warp id
#pragma unroll
    for (int off = 16; off; off >>= 1) {
        s1 += __shfl_xor_sync(0xffffffffu, s1, off);
        s2 += __shfl_xor_sync(0xffffffffu, s2, off);
    }
    int warp = tid >> 5;
    if ((tid & 31) == 0) {
        int slot = (b*NGROUPS + warp)*NTILES + tile;
        g_sum[slot] = s1;
        g_sq[slot]  = s2;
    }
}

// ---------------------------------------------------------------------------
// Kernel 2: reduce per-tile partials into per-(batch,group) mean / rstd
// ---------------------------------------------------------------------------
extern "C" __global__ void gn_stats() {
    __shared__ float sh1[256], sh2[256];
    const int bg = blockIdx.x;        // 0..15
    const int tid = threadIdx.x;
    const float* ps = g_sum + bg*NTILES;
    const float* pq = g_sq  + bg*NTILES;
    float s1 = ps[tid] + ps[tid+256];
    float s2 = pq[tid] + pq[tid+256];
    sh1[tid] = s1; sh2[tid] = s2;
    __syncthreads();
    for (int off = 128; off; off >>= 1) {
        if (tid < off) { sh1[tid] += sh1[tid+off]; sh2[tid] += sh2[tid+off]; }
        __syncthreads();
    }
    if (tid == 0) {
        const float cnt = (float)(GSIZE*NVOX);     // 524288
        float mean = sh1[0] / cnt;
        float var  = sh2[0] / cnt - mean*mean;
        g_stats[bg] = make_float2(mean, rsqrtf(var + 1e-5f));
    }
}

// ---------------------------------------------------------------------------
// Kernel 3: apply GroupNorm affine in place
// ---------------------------------------------------------------------------
extern "C" __global__ void gn_apply(float* __restrict__ out,
                                    const float* __restrict__ gamma,
                                    const float* __restrict__ beta) {
    size_t idx4 = (size_t)blockIdx.x * blockDim.x + threadIdx.x;   // float4 index
    size_t elem = idx4 * 4;
    int b = (int)(elem >> 22);                 // CC*NVOX = 2^22
    int c = (int)((elem >> 15) & 127);         // NVOX = 2^15
    float2 st = g_stats[b*NGROUPS + (c >> 4)];
    float ga = __ldg(&gamma[c]);
    float be = __ldg(&beta[c]);
    float4 v = *(float4*)(out + elem);
    float sc = st.y * ga;
    v.x = (v.x - st.x)*sc + be;
    v.y = (v.y - st.x)*sc + be;
    v.z = (v.z - st.x)*sc + be;
    v.w = (v.w - st.x)*sc + be;
    *(float4*)(out + elem) = v;
}

// ---------------------------------------------------------------------------
extern "C" void kernel_launch(void* const* d_in, const int* in_sizes, int n_in,
                              void* d_out, int out_size) {
    const float* skip  = (const float*)d_in[0];
    const float* dec   = (const float*)d_in[1];
    const float* wq    = (const float*)d_in[2];
    const float* wk    = (const float*)d_in[3];
    const float* wv    = (const float*)d_in[4];
    const float* bq    = (const float*)d_in[5];
    const float* bk    = (const float*)d_in[6];
    const float* bv    = (const float*)d_in[7];
    const float* wo    = (const float*)d_in[8];
    const float* bo    = (const float*)d_in[9];
    const float* gamma = (const float*)d_in[10];
    const float* beta  = (const float*)d_in[11];
    float* out = (float*)d_out;

    const size_t smem = (size_t)(2*SW + SY + SSP + 4*SHN) * sizeof(float); // 176128 B
    cudaFuncSetAttribute(attn_fused, cudaFuncAttributeMaxDynamicSharedMemorySize, (int)smem);

    transpose_w<<<256, 256>>>(wq, wk, wv, wo);
    dim3 grid(NTILES, NB);
    attn_fused<<<grid, 256, smem>>>(skip, dec, bq, bk, bv, bo, out);
    gn_stats<<<NB*NGROUPS, 256>>>();
    gn_apply<<<(NB*CC*NVOX/4)/256, 256>>>(out, gamma, beta);
}